// round 2
// baseline (speedup 1.0000x reference)
#include <cuda_runtime.h>
#include <math.h>

// Problem constants
#define BATCH 4
#define S 160                 // spatial size in each dim
#define R 9                   // erosion radius (9 iterations of 3-window = 19-window)
#define WIN 19
#define TY 32                 // y-tile for pass 2
#define TZ 32                 // z-tile for pass 3
#define NVOX (4LL * 160 * 160 * 160)

// Scratch: two ping-pong erosion buffers (65.5 MB each). Static __device__
// arrays are the allowed scratch mechanism (no allocation calls).
__device__ float g_ex [BATCH * S * S * S];   // after min over x
__device__ float g_exy[BATCH * S * S * S];   // after min over x,y
__device__ double g_acc[3];                  // I, P, T accumulators

__device__ __forceinline__ int clampi(int v, int lo, int hi) {
    return v < lo ? lo : (v > hi ? hi : v);
}

// ---------------------------------------------------------------------------
// Kernel 0: zero the accumulators (graph-replay determinism)
// ---------------------------------------------------------------------------
__global__ void zero_acc_kernel() {
    if (threadIdx.x < 3) g_acc[threadIdx.x] = 0.0;
}

// ---------------------------------------------------------------------------
// Kernel 1: 19-window min along x (contiguous). One block per row (b,z,y).
// ---------------------------------------------------------------------------
__global__ void __launch_bounds__(S) minx_kernel(const float* __restrict__ in,
                                                 float* __restrict__ out) {
    __shared__ float srow[S];
    const long long row = blockIdx.x;          // 0 .. BATCH*S*S-1
    const int t = threadIdx.x;                 // 0 .. 159
    const float* p = in + row * S;
    srow[t] = p[t];
    __syncthreads();
    float m = srow[t];
#pragma unroll
    for (int d = -R; d <= R; ++d) {
        if (d == 0) continue;
        int j = clampi(t + d, 0, S - 1);       // clamped duplicates are min-safe
        m = fminf(m, srow[j]);
    }
    out[row * S + t] = m;
}

// ---------------------------------------------------------------------------
// Kernel 2: 19-window min along y. Block = (b*z, y-tile); 160 threads over x.
// Loads TY+2R = 50 rows of 160 floats into smem (32 KB), 1.56x amplification.
// ---------------------------------------------------------------------------
__global__ void __launch_bounds__(S) miny_kernel(const float* __restrict__ in,
                                                 float* __restrict__ out) {
    __shared__ float s[(TY + 2 * R) * S];      // 50*160*4 = 32000 B
    const int x = threadIdx.x;
    const int ytiles = S / TY;                 // 5
    const int yt = blockIdx.x % ytiles;
    const long long bz = blockIdx.x / ytiles;  // 0 .. BATCH*S-1 (b*S + z)
    const long long base = bz * S * S;
    const int y0 = yt * TY;

#pragma unroll 5
    for (int r = 0; r < TY + 2 * R; ++r) {
        int y = clampi(y0 - R + r, 0, S - 1);
        s[r * S + x] = in[base + (long long)y * S + x];
    }
    __syncthreads();

    for (int ty = 0; ty < TY; ++ty) {
        float m = s[ty * S + x];
#pragma unroll
        for (int d = 1; d < WIN; ++d) m = fminf(m, s[(ty + d) * S + x]);
        out[base + (long long)(y0 + ty) * S + x] = m;
    }
}

// ---------------------------------------------------------------------------
// Kernel 3: 19-window min along z fused with weighted-dice reduction.
// Block = (z-tile, y, b); 160 threads over x. smem holds TZ+18 z-rows of the
// (b, :, y, :) slab. Per-thread fp32 partials -> warp shuffle -> block ->
// double atomicAdd (3200 atomics total).
// ---------------------------------------------------------------------------
__global__ void __launch_bounds__(S) minz_reduce_kernel(const float* __restrict__ exy,
                                                        const float* __restrict__ pred,
                                                        const float* __restrict__ targ) {
    __shared__ float s[(TZ + 2 * R) * S];      // 50*160*4 = 32000 B
    __shared__ float wsum[5][3];               // 5 warps per 160-thread block

    const int x  = threadIdx.x;
    const int zt = blockIdx.x;                 // 0 .. S/TZ-1
    const int y  = blockIdx.y;                 // 0 .. 159
    const int b  = blockIdx.z;                 // 0 .. 3
    const int z0 = zt * TZ;
    const long long bbase = (long long)b * S * S * S;

#pragma unroll 5
    for (int r = 0; r < TZ + 2 * R; ++r) {
        int z = clampi(z0 - R + r, 0, S - 1);
        s[r * S + x] = exy[bbase + ((long long)z * S + y) * S + x];
    }
    __syncthreads();

    float aI = 0.f, aP = 0.f, aT = 0.f;
    for (int tz = 0; tz < TZ; ++tz) {
        float e = s[tz * S + x];
#pragma unroll
        for (int d = 1; d < WIN; ++d) e = fminf(e, s[(tz + d) * S + x]);
        const long long idx = bbase + ((long long)(z0 + tz) * S + y) * S + x;
        const float p = pred[idx];
        const float t = targ[idx];
        const float w = fmaf(t - e, 5.0f, 1.0f);
        const float wp = w * p;
        aI = fmaf(wp, t, aI);
        aP += wp;
        aT = fmaf(w, t, aT);
    }

    // warp reduction (all 5 warps fully populated: 160 threads)
#pragma unroll
    for (int off = 16; off > 0; off >>= 1) {
        aI += __shfl_down_sync(0xFFFFFFFFu, aI, off);
        aP += __shfl_down_sync(0xFFFFFFFFu, aP, off);
        aT += __shfl_down_sync(0xFFFFFFFFu, aT, off);
    }
    const int wid = x >> 5, lane = x & 31;
    if (lane == 0) { wsum[wid][0] = aI; wsum[wid][1] = aP; wsum[wid][2] = aT; }
    __syncthreads();
    if (x == 0) {
        double I = 0.0, P = 0.0, T = 0.0;
#pragma unroll
        for (int wv = 0; wv < 5; ++wv) {
            I += (double)wsum[wv][0];
            P += (double)wsum[wv][1];
            T += (double)wsum[wv][2];
        }
        atomicAdd(&g_acc[0], I);
        atomicAdd(&g_acc[1], P);
        atomicAdd(&g_acc[2], T);
    }
}

// ---------------------------------------------------------------------------
// Kernel 4: finalize scalar loss
// ---------------------------------------------------------------------------
__global__ void finalize_kernel(float* __restrict__ out) {
    const double I = g_acc[0];
    const double P = g_acc[1];
    const double T = g_acc[2];
    const double dice = (2.0 * I + 1e-5) / (P + T + 1e-5);
    out[0] = (float)(1.0 - dice);
}

// ---------------------------------------------------------------------------
extern "C" void kernel_launch(void* const* d_in, const int* in_sizes, int n_in,
                              void* d_out, int out_size) {
    const float* pred = (const float*)d_in[0];
    const float* targ = (const float*)d_in[1];
    float* out = (float*)d_out;
    (void)in_sizes; (void)n_in; (void)out_size;

    float* ex;  cudaGetSymbolAddress((void**)&ex,  g_ex);
    float* exy; cudaGetSymbolAddress((void**)&exy, g_exy);

    zero_acc_kernel<<<1, 32>>>();

    // Pass 1: min over x
    minx_kernel<<<BATCH * S * S, S>>>(targ, ex);

    // Pass 2: min over y
    miny_kernel<<<BATCH * S * (S / TY), S>>>(ex, exy);

    // Pass 3: min over z + fused reduction
    dim3 g3(S / TZ, S, BATCH);
    minz_reduce_kernel<<<g3, S>>>(exy, pred, targ);

    // Finalize
    finalize_kernel<<<1, 1>>>(out);
}

// round 3
// speedup vs baseline: 1.0380x; 1.0380x over previous
#include <cuda_runtime.h>
#include <math.h>

#define S 160
#define R 9                  // 9 iterations of 3-window == one 19-window (clamped)
#define TY 32                // y-tile (pass A)
#define TZ 32                // z-tile (pass B)
#define NT 480               // 160 x-lanes * 3 row-groups = 15 warps

// Scratch (static __device__ = allowed scratch; no allocation calls)
__device__ float  g_exy[4 * S * S * S];   // target after min over x,y
__device__ double g_acc[3];               // I, P, T accumulators

__device__ __forceinline__ int clampi(int v, int lo, int hi) {
    return v < lo ? lo : (v > hi ? hi : v);
}

// ---------------------------------------------------------------------------
// Kernel 0: zero accumulators (graph-replay determinism)
// ---------------------------------------------------------------------------
__global__ void zero_acc_kernel() {
    if (threadIdx.x < 3) g_acc[threadIdx.x] = 0.0;
}

// ---------------------------------------------------------------------------
// Pass A: fused 19-window min over y then x.
// Block = (ytile, z, b), 480 threads (x = tid%160, ty = tid/160).
// Dynamic smem: A[50][160] raw target rows (y-halo), C[32][160] y-min result.
// A is reused as the m4x buffer after the y stage.
// ---------------------------------------------------------------------------
__global__ void __launch_bounds__(NT) minxy_kernel(const float* __restrict__ in,
                                                   float* __restrict__ out) {
    extern __shared__ float sm[];
    float* A = sm;               // 50*160 floats
    float* C = sm + (TY + 2 * R) * S;  // 32*160 floats

    const int tid = threadIdx.x;
    const int x   = tid % S;
    const int ty  = tid / S;          // 0..2
    const int yt  = blockIdx.x;       // 0..4
    const int z   = blockIdx.y;       // 0..159
    const int b   = blockIdx.z;       // 0..3
    const int y0  = yt * TY;
    const long long base = ((long long)b * S + z) * S * S;

    // Load 50 y-rows (clamped halo), coalesced in x.
    for (int r = ty; r < TY + 2 * R; r += 3) {
        int y = clampi(y0 - R + r, 0, S - 1);
        A[r * S + x] = in[base + (long long)y * S + x];
    }
    __syncthreads();

    // y-min: groups of 4 outputs share a 16-row core min.
    // smem row r <-> global y0-9+r; output row o windows smem rows [o, o+18].
    {
        const float* col = A + x;
        for (int g = ty; g < TY / 4; g += 3) {
            const int o = 4 * g;
            float c0 = col[(o + 3) * S];
#pragma unroll
            for (int d = 4; d <= 18; ++d) c0 = fminf(c0, col[(o + d) * S]);
            const float a0 = col[(o + 0) * S], a1 = col[(o + 1) * S];
            const float a2 = col[(o + 2) * S];
            const float b0 = col[(o + 19) * S], b1 = col[(o + 20) * S];
            const float b2 = col[(o + 21) * S];
            C[(o + 0) * S + x] = fminf(fminf(a0, a1), fminf(a2, c0));
            C[(o + 1) * S + x] = fminf(fminf(a1, a2), fminf(c0, b0));
            C[(o + 2) * S + x] = fminf(fminf(a2, c0), fminf(b0, b1));
            C[(o + 3) * S + x] = fminf(fminf(c0, b0), fminf(b1, b2));
        }
    }
    __syncthreads();

    // m4x stage into A (raw rows dead now): M4[row][x] = min(C[row][x..x+3]) clamped
    float* M4 = A;
    for (int i = tid; i < TY * S; i += NT) {
        const int row = i / S, xx = i % S;
        const float* cr = C + row * S;
        float m = fminf(cr[xx], cr[min(xx + 1, S - 1)]);
        m = fminf(m, fminf(cr[min(xx + 2, S - 1)], cr[min(xx + 3, S - 1)]));
        M4[i] = m;
    }
    __syncthreads();

    // Combine: win19_x = min(m4[x-9], m4[x-5], m4[x-1], m4[x+3], C[x+7..x+9])
    for (int i = tid; i < TY * S; i += NT) {
        const int row = i / S, xx = i % S;
        const float* mr = M4 + row * S;
        const float* cr = C + row * S;
        float m = fminf(mr[max(xx - 9, 0)], mr[max(xx - 5, 0)]);
        m = fminf(m, fminf(mr[max(xx - 1, 0)], mr[min(xx + 3, S - 1)]));
        m = fminf(m, fminf(cr[min(xx + 7, S - 1)], cr[min(xx + 8, S - 1)]));
        m = fminf(m, cr[min(xx + 9, S - 1)]);
        out[base + (long long)(y0 + row) * S + xx] = m;
    }
}

// ---------------------------------------------------------------------------
// Pass B: 19-window min over z fused with the weighted-dice reduction.
// Block = (ztile, y, b), 480 threads. smem = 50 z-rows of the (b,:,y,:) slab.
// ---------------------------------------------------------------------------
__global__ void __launch_bounds__(NT) minz_reduce_kernel(const float* __restrict__ exy,
                                                         const float* __restrict__ pred,
                                                         const float* __restrict__ targ) {
    __shared__ float s[(TZ + 2 * R) * S];   // 32000 B
    __shared__ float wsum[NT / 32][3];

    const int tid = threadIdx.x;
    const int x   = tid % S;
    const int ty  = tid / S;
    const int zt  = blockIdx.x;       // 0..4
    const int y   = blockIdx.y;       // 0..159
    const int b   = blockIdx.z;       // 0..3
    const int z0  = zt * TZ;
    const long long bbase = (long long)b * S * S * S;

    for (int r = ty; r < TZ + 2 * R; r += 3) {
        int z = clampi(z0 - R + r, 0, S - 1);
        s[r * S + x] = exy[bbase + ((long long)z * S + y) * S + x];
    }
    __syncthreads();

    float aI = 0.f, aP = 0.f, aT = 0.f;
    const float* col = s + x;
    for (int g = ty; g < TZ / 4; g += 3) {
        const int o = 4 * g;
        float c0 = col[(o + 3) * S];
#pragma unroll
        for (int d = 4; d <= 18; ++d) c0 = fminf(c0, col[(o + d) * S]);
        const float a0 = col[(o + 0) * S], a1 = col[(o + 1) * S];
        const float a2 = col[(o + 2) * S];
        const float b0 = col[(o + 19) * S], b1 = col[(o + 20) * S];
        const float b2 = col[(o + 21) * S];
        float e[4];
        e[0] = fminf(fminf(a0, a1), fminf(a2, c0));
        e[1] = fminf(fminf(a1, a2), fminf(c0, b0));
        e[2] = fminf(fminf(a2, c0), fminf(b0, b1));
        e[3] = fminf(fminf(c0, b0), fminf(b1, b2));

        const long long idx0 = bbase + ((long long)(z0 + o) * S + y) * S + x;
#pragma unroll
        for (int k = 0; k < 4; ++k) {
            const long long idx = idx0 + (long long)k * S * S;
            const float p = pred[idx];
            const float t = targ[idx];
            const float w  = fmaf(t - e[k], 5.0f, 1.0f);
            const float wp = w * p;
            aI = fmaf(wp, t, aI);
            aP += wp;
            aT = fmaf(w, t, aT);
        }
    }

    // warp reduce (all 15 warps fully populated)
#pragma unroll
    for (int off = 16; off > 0; off >>= 1) {
        aI += __shfl_down_sync(0xFFFFFFFFu, aI, off);
        aP += __shfl_down_sync(0xFFFFFFFFu, aP, off);
        aT += __shfl_down_sync(0xFFFFFFFFu, aT, off);
    }
    const int wid = tid >> 5, lane = tid & 31;
    if (lane == 0) { wsum[wid][0] = aI; wsum[wid][1] = aP; wsum[wid][2] = aT; }
    __syncthreads();
    if (tid == 0) {
        double I = 0.0, P = 0.0, T = 0.0;
#pragma unroll
        for (int w = 0; w < NT / 32; ++w) {
            I += (double)wsum[w][0];
            P += (double)wsum[w][1];
            T += (double)wsum[w][2];
        }
        atomicAdd(&g_acc[0], I);
        atomicAdd(&g_acc[1], P);
        atomicAdd(&g_acc[2], T);
    }
}

// ---------------------------------------------------------------------------
// Finalize
// ---------------------------------------------------------------------------
__global__ void finalize_kernel(float* __restrict__ out) {
    const double dice = (2.0 * g_acc[0] + 1e-5) / (g_acc[1] + g_acc[2] + 1e-5);
    out[0] = (float)(1.0 - dice);
}

// ---------------------------------------------------------------------------
extern "C" void kernel_launch(void* const* d_in, const int* in_sizes, int n_in,
                              void* d_out, int out_size) {
    const float* pred = (const float*)d_in[0];
    const float* targ = (const float*)d_in[1];
    float* out = (float*)d_out;
    (void)in_sizes; (void)n_in; (void)out_size;

    float* exy; cudaGetSymbolAddress((void**)&exy, g_exy);

    const int smemA = ((TY + 2 * R) + TY) * S * (int)sizeof(float);  // 52480 B
    cudaFuncSetAttribute(minxy_kernel, cudaFuncAttributeMaxDynamicSharedMemorySize, smemA);

    zero_acc_kernel<<<1, 32>>>();

    dim3 grid(S / TY, S, 4);           // (5, 160, 4)
    minxy_kernel<<<grid, NT, smemA>>>(targ, exy);

    dim3 gridB(S / TZ, S, 4);
    minz_reduce_kernel<<<gridB, NT>>>(exy, pred, targ);

    finalize_kernel<<<1, 1>>>(out);
}

// round 4
// speedup vs baseline: 1.6390x; 1.5789x over previous
#include <cuda_runtime.h>
#include <math.h>

#define S   160
#define SQ  40          // S/4 float4 quads per row
#define R   9           // 9x 3-window erosion == one 19-window (clamped)
#define TY  32
#define TZ  32
#define NT  320         // 40 quads * 8 groups

// Scratch (static __device__ = allowed; no allocation calls)
__device__ float  g_exy[4 * S * S * S];
__device__ double g_acc[3];

__device__ __forceinline__ int clampi(int v, int lo, int hi) {
    return v < lo ? lo : (v > hi ? hi : v);
}
__device__ __forceinline__ float4 f4min(float4 a, float4 b) {
    return make_float4(fminf(a.x, b.x), fminf(a.y, b.y),
                       fminf(a.z, b.z), fminf(a.w, b.w));
}

__global__ void zero_acc_kernel() {
    if (threadIdx.x < 3) g_acc[threadIdx.x] = 0.0;
}

// ---------------------------------------------------------------------------
// Pass A: fused 19-min over y then x, one (b,z) plane y-tile per block.
// 320 threads: q = tid%40 (x-quad), g = tid/40 (row-group).
// smem: A[50][40] float4 raw rows, C[32][40] float4 y-min rows.
// ---------------------------------------------------------------------------
__global__ void __launch_bounds__(NT) minxy_kernel(const float4* __restrict__ in4,
                                                   float4* __restrict__ out4) {
    extern __shared__ float4 sm4[];
    float4* A = sm4;                 // 50*40
    float4* C = sm4 + 50 * SQ;       // 32*40

    const int tid = threadIdx.x;
    const int q   = tid % SQ;
    const int g   = tid / SQ;        // 0..7
    const int y0  = blockIdx.x * TY;
    const int z   = blockIdx.y;
    const int b   = blockIdx.z;
    const long long base4 = (long long)(b * S + z) * S * SQ;

    // Load 50 y-rows (clamped halo), float4-coalesced.
    for (int i = tid; i < 50 * SQ; i += NT) {
        const int r = i / SQ, qq = i % SQ;
        const int y = clampi(y0 - R + r, 0, S - 1);
        A[r * SQ + qq] = in4[base4 + y * SQ + qq];
    }
    __syncthreads();

    // y-min: group of 4 outputs shares a 16-row tree-min core.
    {
        const int o = 4 * g;
        const float4* col = A + q;
        float4 p0 = f4min(col[(o + 3) * SQ],  col[(o + 4) * SQ]);
        float4 p1 = f4min(col[(o + 5) * SQ],  col[(o + 6) * SQ]);
        float4 p2 = f4min(col[(o + 7) * SQ],  col[(o + 8) * SQ]);
        float4 p3 = f4min(col[(o + 9) * SQ],  col[(o + 10) * SQ]);
        float4 p4 = f4min(col[(o + 11) * SQ], col[(o + 12) * SQ]);
        float4 p5 = f4min(col[(o + 13) * SQ], col[(o + 14) * SQ]);
        float4 p6 = f4min(col[(o + 15) * SQ], col[(o + 16) * SQ]);
        float4 p7 = f4min(col[(o + 17) * SQ], col[(o + 18) * SQ]);
        float4 core = f4min(f4min(f4min(p0, p1), f4min(p2, p3)),
                            f4min(f4min(p4, p5), f4min(p6, p7)));
        float4 a0 = col[(o + 0) * SQ],  a1 = col[(o + 1) * SQ];
        float4 a2 = col[(o + 2) * SQ];
        float4 b0 = col[(o + 19) * SQ], b1 = col[(o + 20) * SQ];
        float4 b2 = col[(o + 21) * SQ];
        C[(o + 0) * SQ + q] = f4min(f4min(a0, a1),   f4min(a2, core));
        C[(o + 1) * SQ + q] = f4min(f4min(a1, a2),   f4min(core, b0));
        C[(o + 2) * SQ + q] = f4min(f4min(a2, core), f4min(b0, b1));
        C[(o + 3) * SQ + q] = f4min(f4min(core, b0), f4min(b1, b2));
    }
    __syncthreads();

    // x-min: per (row, quad) gather 7 float4 quads (quad-clamped, min-safe),
    // unpack to v[28] (v[i] <-> x = 4q-12+i), tree core v[6..21].
#pragma unroll
    for (int k = 0; k < 4; ++k) {
        const int i = tid + NT * k;          // 0..1279 exactly
        const int row = i / SQ, qq = i % SQ;
        float v[28];
#pragma unroll
        for (int dq = -3; dq <= 3; ++dq) {
            const float4 c = C[row * SQ + clampi(qq + dq, 0, SQ - 1)];
            const int o = (dq + 3) * 4;
            v[o] = c.x; v[o + 1] = c.y; v[o + 2] = c.z; v[o + 3] = c.w;
        }
        float t0 = fminf(v[6],  v[7]),  t1 = fminf(v[8],  v[9]);
        float t2 = fminf(v[10], v[11]), t3 = fminf(v[12], v[13]);
        float t4 = fminf(v[14], v[15]), t5 = fminf(v[16], v[17]);
        float t6 = fminf(v[18], v[19]), t7 = fminf(v[20], v[21]);
        float core = fminf(fminf(fminf(t0, t1), fminf(t2, t3)),
                           fminf(fminf(t4, t5), fminf(t6, t7)));
        float4 r4;
        r4.x = fminf(core, fminf(v[3],  fminf(v[4],  v[5])));
        r4.y = fminf(core, fminf(v[4],  fminf(v[5],  v[22])));
        r4.z = fminf(core, fminf(v[5],  fminf(v[22], v[23])));
        r4.w = fminf(core, fminf(v[22], fminf(v[23], v[24])));
        out4[base4 + (long long)(y0 + row) * SQ + qq] = r4;
    }
}

// ---------------------------------------------------------------------------
// Pass B: 19-min over z fused with the weighted-dice reduction.
// ---------------------------------------------------------------------------
__global__ void __launch_bounds__(NT) minz_reduce_kernel(const float4* __restrict__ exy4,
                                                         const float4* __restrict__ pred4,
                                                         const float4* __restrict__ targ4) {
    __shared__ float4 s4[50 * SQ];           // 32000 B
    __shared__ float  wsum[NT / 32][3];

    const int tid = threadIdx.x;
    const int q   = tid % SQ;
    const int g   = tid / SQ;                // 0..7
    const int o   = 4 * g;
    const int z0  = blockIdx.x * TZ;
    const int y   = blockIdx.y;
    const int b   = blockIdx.z;
    const long long bbase4 = (long long)b * S * S * SQ;

    for (int i = tid; i < 50 * SQ; i += NT) {
        const int r = i / SQ, qq = i % SQ;
        const int z = clampi(z0 - R + r, 0, S - 1);
        s4[r * SQ + qq] = exy4[bbase4 + (long long)z * S * SQ + y * SQ + qq];
    }
    __syncthreads();

    const float4* col = s4 + q;
    float4 p0 = f4min(col[(o + 3) * SQ],  col[(o + 4) * SQ]);
    float4 p1 = f4min(col[(o + 5) * SQ],  col[(o + 6) * SQ]);
    float4 p2 = f4min(col[(o + 7) * SQ],  col[(o + 8) * SQ]);
    float4 p3 = f4min(col[(o + 9) * SQ],  col[(o + 10) * SQ]);
    float4 p4 = f4min(col[(o + 11) * SQ], col[(o + 12) * SQ]);
    float4 p5 = f4min(col[(o + 13) * SQ], col[(o + 14) * SQ]);
    float4 p6 = f4min(col[(o + 15) * SQ], col[(o + 16) * SQ]);
    float4 p7 = f4min(col[(o + 17) * SQ], col[(o + 18) * SQ]);
    float4 core = f4min(f4min(f4min(p0, p1), f4min(p2, p3)),
                        f4min(f4min(p4, p5), f4min(p6, p7)));
    float4 a0 = col[(o + 0) * SQ],  a1 = col[(o + 1) * SQ];
    float4 a2 = col[(o + 2) * SQ];
    float4 b0 = col[(o + 19) * SQ], b1 = col[(o + 20) * SQ];
    float4 b2 = col[(o + 21) * SQ];
    float4 e[4];
    e[0] = f4min(f4min(a0, a1),   f4min(a2, core));
    e[1] = f4min(f4min(a1, a2),   f4min(core, b0));
    e[2] = f4min(f4min(a2, core), f4min(b0, b1));
    e[3] = f4min(f4min(core, b0), f4min(b1, b2));

    float aI = 0.f, aP = 0.f, aT = 0.f;
#pragma unroll
    for (int j = 0; j < 4; ++j) {
        const long long idx4 = bbase4 + (long long)(z0 + o + j) * S * SQ + y * SQ + q;
        const float4 p = pred4[idx4];
        const float4 t = targ4[idx4];
        const float4 ev = e[j];
        float w, wp;
        w = fmaf(t.x - ev.x, 5.0f, 1.0f); wp = w * p.x;
        aI = fmaf(wp, t.x, aI); aP += wp; aT = fmaf(w, t.x, aT);
        w = fmaf(t.y - ev.y, 5.0f, 1.0f); wp = w * p.y;
        aI = fmaf(wp, t.y, aI); aP += wp; aT = fmaf(w, t.y, aT);
        w = fmaf(t.z - ev.z, 5.0f, 1.0f); wp = w * p.z;
        aI = fmaf(wp, t.z, aI); aP += wp; aT = fmaf(w, t.z, aT);
        w = fmaf(t.w - ev.w, 5.0f, 1.0f); wp = w * p.w;
        aI = fmaf(wp, t.w, aI); aP += wp; aT = fmaf(w, t.w, aT);
    }

#pragma unroll
    for (int off = 16; off > 0; off >>= 1) {
        aI += __shfl_down_sync(0xFFFFFFFFu, aI, off);
        aP += __shfl_down_sync(0xFFFFFFFFu, aP, off);
        aT += __shfl_down_sync(0xFFFFFFFFu, aT, off);
    }
    const int wid = tid >> 5, lane = tid & 31;
    if (lane == 0) { wsum[wid][0] = aI; wsum[wid][1] = aP; wsum[wid][2] = aT; }
    __syncthreads();
    if (tid == 0) {
        double I = 0.0, P = 0.0, T = 0.0;
#pragma unroll
        for (int w = 0; w < NT / 32; ++w) {
            I += (double)wsum[w][0];
            P += (double)wsum[w][1];
            T += (double)wsum[w][2];
        }
        atomicAdd(&g_acc[0], I);
        atomicAdd(&g_acc[1], P);
        atomicAdd(&g_acc[2], T);
    }
}

__global__ void finalize_kernel(float* __restrict__ out) {
    const double dice = (2.0 * g_acc[0] + 1e-5) / (g_acc[1] + g_acc[2] + 1e-5);
    out[0] = (float)(1.0 - dice);
}

// ---------------------------------------------------------------------------
extern "C" void kernel_launch(void* const* d_in, const int* in_sizes, int n_in,
                              void* d_out, int out_size) {
    const float4* pred = (const float4*)d_in[0];
    const float4* targ = (const float4*)d_in[1];
    float* out = (float*)d_out;
    (void)in_sizes; (void)n_in; (void)out_size;

    float* exy; cudaGetSymbolAddress((void**)&exy, g_exy);

    const int smemA = (50 + TY) * SQ * (int)sizeof(float4);   // 52480 B
    cudaFuncSetAttribute(minxy_kernel, cudaFuncAttributeMaxDynamicSharedMemorySize, smemA);

    zero_acc_kernel<<<1, 32>>>();

    dim3 grid(S / TY, S, 4);
    minxy_kernel<<<grid, NT, smemA>>>(targ, (float4*)exy);

    dim3 gridB(S / TZ, S, 4);
    minz_reduce_kernel<<<gridB, NT>>>((const float4*)exy, pred, targ);

    finalize_kernel<<<1, 1>>>(out);
}